// round 16
// baseline (speedup 1.0000x reference)
#include <cuda_runtime.h>
#include <cuda_bf16.h>
#include <cstdint>
#include <math.h>

#define NB   64
#define NT   128
#define BT   8192
#define H    1024
#define DIN  2048
#define G4   4096
#define NH1  256
#define NANS 1000
#define NCTA 128u

// ---------------- device scratch ----------------
__device__ float g_X1[(size_t)BT * G4];          // [t][b][4H] (includes +b1)
__device__ unsigned g_bar;
// h in bf16 A-fragment layout: [kc(64)][mt(4)][lane(32)][reg(4)] u32
__device__ __align__(16) uint32_t g_h1p[2][32768];
__device__ __align__(16) uint32_t g_h2p[2][32768];
// step weights, B-fragment layout: [bx(128)][kc][g(4)][lane(32)] uint2
__device__ __align__(16) uint32_t g_W1p[128 * 64 * 4 * 32 * 2];     // 8 MB
__device__ __align__(16) uint32_t g_W2p[128 * 128 * 4 * 32 * 2];    // 16 MB
// xproj operands (fragment-packed)
__device__ __align__(16) uint32_t g_Ax[(size_t)128 * 128 * 4 * 32 * 4];  // 32 MB
__device__ __align__(16) uint32_t g_Wx[(size_t)64 * 128 * 8 * 32 * 2];   // 16 MB
// head: lstm_out bf16 A-frag [mb(128)][kc(64)][mt(4)][lane(32)][reg(4)]
__device__ __align__(16) uint32_t g_LOp[(size_t)128 * 64 * 4 * 32 * 4];  // 16 MB
// hid bf16 A-frag [mb(128)][kc(16)][mt][lane][reg]
__device__ __align__(16) uint32_t g_HIDp[(size_t)128 * 16 * 4 * 32 * 4]; // 4 MB
__device__ __align__(16) uint32_t g_Wp1p[4 * 64 * 8 * 32 * 2];
__device__ __align__(16) uint32_t g_Wp2p[16 * 16 * 8 * 32 * 2];

// fast activations
__device__ __forceinline__ float fsig(float x) {
    return __fdividef(1.f, 1.f + __expf(-x));
}
__device__ __forceinline__ float ftanh_(float x) {
    return fmaf(2.f, fsig(2.f * x), -1.f);
}
__device__ __forceinline__ uint32_t pk(float x, float y) {
    __nv_bfloat162 v = __floats2bfloat162_rn(x, y);
    return *reinterpret_cast<uint32_t*>(&v);
}
__device__ __forceinline__ void mmabf(float c[4], uint4 a, uint2 b) {
    asm volatile(
        "mma.sync.aligned.m16n8k16.row.col.f32.bf16.bf16.f32 "
        "{%0,%1,%2,%3},{%4,%5,%6,%7},{%8,%9},{%0,%1,%2,%3};"
        : "+f"(c[0]), "+f"(c[1]), "+f"(c[2]), "+f"(c[3])
        : "r"(a.x), "r"(a.y), "r"(a.z), "r"(a.w), "r"(b.x), "r"(b.y));
}
__device__ __forceinline__ void cp16(void* smem, const void* g) {
    uint32_t s = (uint32_t)__cvta_generic_to_shared(smem);
    asm volatile("cp.async.cg.shared.global [%0], [%1], 16;" :: "r"(s), "l"(g));
}
__device__ __forceinline__ void cp_commit() { asm volatile("cp.async.commit_group;"); }
__device__ __forceinline__ void cp_wait2()  { asm volatile("cp.async.wait_group 2;"); }
__device__ __forceinline__ void cp_wait0()  { asm volatile("cp.async.wait_group 0;"); }

// global barrier: release-arrive + acquire-poll
__device__ __forceinline__ void gbar(unsigned target) {
    __syncthreads();
    if (threadIdx.x == 0) {
        unsigned* bp = &g_bar;
        asm volatile("red.release.gpu.global.add.u32 [%0], %1;"
                     :: "l"(bp), "r"(1u) : "memory");
        unsigned v;
        do {
            asm volatile("ld.acquire.gpu.global.u32 %0, [%1];"
                         : "=r"(v) : "l"(bp) : "memory");
        } while (v < target);
    }
    __syncthreads();
}

// ---------------- init ----------------
__global__ void k_init_state() {
    int i = blockIdx.x * blockDim.x + threadIdx.x;
    if (i == 0) g_bar = 0u;
    if (i < 32768) { g_h1p[0][i] = 0u; g_h2p[0][i] = 0u; }
}

// ---------------- unified pack kernel (job = blockIdx.y) ---------------------
__global__ void k_pack_all(
    const float* __restrict__ W_hh1, const float* __restrict__ W_ih2,
    const float* __restrict__ W_hh2, const float* __restrict__ d1,
    const float* __restrict__ d2,   const float* __restrict__ W_ih1,
    const float* __restrict__ Wp1,  const float* __restrict__ Wp2)
{
    const int job = blockIdx.y;
    const int gid = blockIdx.x * blockDim.x + threadIdx.x;
    const int stride = gridDim.x * blockDim.x;

    if (job == 0) {
        uint2* out = (uint2*)g_W1p;
        for (int idx = gid; idx < 128 * 64 * 4 * 32; idx += stride) {
            int lane = idx & 31;
            int t1 = idx >> 5;  int g = t1 & 3;
            int t2 = t1 >> 2;   int kc = t2 & 63; int bx = t2 >> 6;
            int rr = lane >> 2, cc = lane & 3;
            const float* p = W_hh1 + (size_t)(g * H + bx * 8 + rr) * H + kc * 16 + cc * 2;
            uint2 v; v.x = pk(p[0], p[1]); v.y = pk(p[8], p[9]);
            out[idx] = v;
        }
    } else if (job == 1) {
        uint2* out = (uint2*)g_W2p;
        for (int idx = gid; idx < 128 * 128 * 4 * 32; idx += stride) {
            int lane = idx & 31;
            int t1 = idx >> 5;  int g = t1 & 3;
            int t2 = t1 >> 2;   int kc = t2 & 127; int bx = t2 >> 7;
            int rr = lane >> 2, cc = lane & 3;
            int row = g * H + bx * 8 + rr;
            const float* W = W_ih2; int k0 = kc * 16 + cc * 2;
            if (kc >= 64) { W = W_hh2; k0 -= 1024; }
            const float* p = W + (size_t)row * H + k0;
            uint2 v; v.x = pk(p[0], p[1]); v.y = pk(p[8], p[9]);
            out[idx] = v;
        }
    } else if (job == 2) {
        uint4* out = (uint4*)g_Ax;
        for (int idx = gid; idx < 128 * 128 * 4 * 32; idx += stride) {
            int lane = idx & 31;
            int t1 = idx >> 5;
            int mt = t1 & 3; t1 >>= 2;
            int kc = t1 & 127;
            int mb = t1 >> 7;
            int rr = lane >> 2, cc = lane & 3;
            int r0 = mb * 64 + mt * 16 + rr, r1 = r0 + 8;
            int k0 = kc * 16 + cc * 2;
            const float *s0, *s1;
            if (k0 < 1024) { s0 = d1 + (size_t)r0 * 1024 + k0;        s1 = d1 + (size_t)r1 * 1024 + k0; }
            else           { s0 = d2 + (size_t)r0 * 1024 + k0 - 1024; s1 = d2 + (size_t)r1 * 1024 + k0 - 1024; }
            uint4 v;
            v.x = pk(s0[0], s0[1]);
            v.y = pk(s1[0], s1[1]);
            v.z = pk(s0[8], s0[9]);
            v.w = pk(s1[8], s1[9]);
            out[idx] = v;
        }
    } else if (job == 3) {
        uint2* out = (uint2*)g_Wx;
        for (int idx = gid; idx < 64 * 128 * 8 * 32; idx += stride) {
            int lane = idx & 31;
            int t1 = idx >> 5;
            int c = t1 & 7; t1 >>= 3;
            int kc = t1 & 127;
            int nb = t1 >> 7;
            int rr = lane >> 2, cc = lane & 3;
            const float* p = W_ih1 + (size_t)(nb * 64 + c * 8 + rr) * DIN + kc * 16 + cc * 2;
            uint2 v; v.x = pk(p[0], p[1]); v.y = pk(p[8], p[9]);
            out[idx] = v;
        }
    } else if (job == 4) {
        uint2* out = (uint2*)g_Wp1p;
        for (int idx = gid; idx < 4 * 64 * 8 * 32; idx += stride) {
            int lane = idx & 31;
            int t1 = idx >> 5;
            int c = t1 & 7; t1 >>= 3;
            int kc = t1 & 63;
            int nb = t1 >> 6;
            int rr = lane >> 2, cc = lane & 3;
            int n  = nb * 64 + c * 8 + rr;
            int k0 = kc * 16 + cc * 2;
            uint2 v;
            v.x = pk(Wp1[(size_t)k0 * NH1 + n],       Wp1[(size_t)(k0 + 1) * NH1 + n]);
            v.y = pk(Wp1[(size_t)(k0 + 8) * NH1 + n], Wp1[(size_t)(k0 + 9) * NH1 + n]);
            out[idx] = v;
        }
    } else {
        uint2* out = (uint2*)g_Wp2p;
        for (int idx = gid; idx < 16 * 16 * 8 * 32; idx += stride) {
            int lane = idx & 31;
            int t1 = idx >> 5;
            int c = t1 & 7; t1 >>= 3;
            int kc = t1 & 15;
            int nb = t1 >> 4;
            int rr = lane >> 2, cc = lane & 3;
            int n  = nb * 64 + c * 8 + rr;
            int k0 = kc * 16 + cc * 2;
            float a0 = 0.f, a1 = 0.f, b0 = 0.f, b1 = 0.f;
            if (n < NANS) {
                a0 = Wp2[(size_t)k0 * NANS + n];       a1 = Wp2[(size_t)(k0 + 1) * NANS + n];
                b0 = Wp2[(size_t)(k0 + 8) * NANS + n]; b1 = Wp2[(size_t)(k0 + 9) * NANS + n];
            }
            uint2 v; v.x = pk(a0, a1); v.y = pk(b0, b1);
            out[idx] = v;
        }
    }
}

// =================== xproj: bf16 mma, 128x256 tile, 64x64 warp tiles ========
// 8 warps = (wm 0..1) x (wn 0..3). Warp sub-tile 64x64: 128 acc regs/thread.
// smem reads/iter: A 16KB*4 + B 32KB*2 = 128KB (was 192KB). 256 thr, 192KB smem.
__global__ __launch_bounds__(256) void k_xprojb(const float* __restrict__ bias)
{
    extern __shared__ uint4 sm[];
    const int tid = threadIdx.x, wid = tid >> 5, lane = tid & 31;
    const int wm = wid & 1, wn = wid >> 1;
    const int rr = lane >> 2, cc = lane & 3;
    const int nb = blockIdx.x, mb = blockIdx.y;
    float acc[4][8][4] = {};                    // [m-frag][n-frag][reg]
    const uint4* Abase = (const uint4*)g_Ax + (size_t)(mb * 2) * 16384;
    const uint4* Bbase = (const uint4*)g_Wx + (size_t)(nb * 4) * 16384;

    auto loadst = [&](int it) {
        if (it < 32) {
            uint4* dst = sm + (it & 3) * 3072;
            const int kc0 = it * 4;
#pragma unroll
            for (int e = 0; e < 12; e++) {
                int flat = e * 256 + tid;
                const uint4* src;
                if (flat < 1024) {                  // A slot q = h*4+kcl
                    int q = flat >> 7, i = flat & 127;
                    int h = q >> 2, kcl = q & 3;
                    src = Abase + (size_t)h * 16384 + (kc0 + kcl) * 128 + i;
                } else {                            // B slot q = cb*4+kcl
                    int f2 = flat - 1024;
                    int q = f2 >> 7, i = f2 & 127;
                    int cb = q >> 2, kcl = q & 3;
                    src = Bbase + (size_t)cb * 16384 + (kc0 + kcl) * 128 + i;
                }
                cp16(&dst[flat], src);
            }
        }
        cp_commit();
    };
    loadst(0); loadst(1); loadst(2);
    for (int it = 0; it < 32; it++) {
        cp_wait2(); __syncthreads();
        loadst(it + 3);
        const uint4* SA = sm + (it & 3) * 3072;
        const uint2* SB = (const uint2*)(SA + 1024);
#pragma unroll
        for (int kcl = 0; kcl < 4; kcl++) {
            // A frags: warp rows wm*64 + mf*16 -> slot (h=wm, mtl=mf)
            uint4 a[4];
#pragma unroll
            for (int mf = 0; mf < 4; mf++)
                a[mf] = SA[(wm * 4 + kcl) * 128 + mf * 32 + lane];
#pragma unroll
            for (int c = 0; c < 8; c++) {
                uint2 b = SB[((wn * 4 + kcl) * 8 + c) * 32 + lane];
#pragma unroll
                for (int mf = 0; mf < 4; mf++)
                    mmabf(acc[mf][c], a[mf], b);
            }
        }
    }
#pragma unroll
    for (int mf = 0; mf < 4; mf++)
#pragma unroll
    for (int c = 0; c < 8; c++) {
        int col = nb * 256 + wn * 64 + c * 8 + cc * 2;
        float b0 = bias[col], b1 = bias[col + 1];
#pragma unroll
        for (int hh = 0; hh < 2; hh++) {
            int m = mb * 128 + wm * 64 + mf * 16 + rr + hh * 8;
            int tt = m & 127, bb = m >> 7;
            float* o = g_X1 + ((size_t)tt * NB + bb) * G4 + col;
            o[0] = acc[mf][c][hh * 2 + 0] + b0;
            o[1] = acc[mf][c][hh * 2 + 1] + b1;
        }
    }
}

// =================== persistent recurrence kernel (unchanged R15) ===========
__global__ __launch_bounds__(256) void k_recur(const float* __restrict__ b2)
{
    extern __shared__ uint4 sm[];
    const int tid = threadIdx.x, wid = tid >> 5, lane = tid & 31;
    const int mt = wid & 3, s = wid >> 2;
    const int rr = lane >> 2, cc = lane & 3;
    const int bx = blockIdx.x;
    float* Gs   = (float*)sm;
    float* Gs2  = (float*)(sm + 576);
    const uint2* Wsm1 = (const uint2*)(sm + 1152);
    const uint2* Wsm2 = (const uint2*)(sm + 5248);
    float* XSf  = (float*)(sm + 13440);
    float* HRf  = (float*)(sm + 14016);     // [2][64][10]
    const int j = bx * 8 + cc * 2;
    const int j0 = bx * 8;
    const int fragoff = mt * 32 + lane;

    {
        const uint4* w1 = (const uint4*)g_W1p + (size_t)bx * 4096;
        for (int i = tid; i < 4096; i += 256) cp16(&sm[1152 + i], &w1[i]);
        const uint4* w2 = (const uint4*)g_W2p + (size_t)bx * 8192;
        for (int i = tid; i < 8192; i += 256) cp16(&sm[5248 + i], &w2[i]);
        cp_commit(); cp_wait0(); __syncthreads();
    }

    float2 b2i = make_float2(b2[j],         b2[j + 1]);
    float2 b2f = make_float2(b2[H + j],     b2[H + j + 1]);
    float2 b2g = make_float2(b2[2 * H + j], b2[2 * H + j + 1]);
    float2 b2o = make_float2(b2[3 * H + j], b2[3 * H + j + 1]);

    const int em0 = mt * 16 + rr, em1 = em0 + 8;
    float2 c1v[2] = { make_float2(0.f, 0.f), make_float2(0.f, 0.f) };
    float2 c2v[2] = { make_float2(0.f, 0.f), make_float2(0.f, 0.f) };

    auto stageX = [&](int tt) {
        const float* Xt = g_X1 + (size_t)tt * NB * G4;
#pragma unroll
        for (int e = 0; e < 2; e++) {
            int i = tid + e * 256;
            int m = i >> 3, seg = i & 7;
            int g = seg >> 1, half = seg & 1;
            cp16(&XSf[m * 36 + g * 8 + half * 4],
                 Xt + (size_t)m * G4 + g * H + j0 + half * 4);
        }
        cp_commit();
    };

    // prologue: L1(0) = cell(X1[0]) by s==0
    {
        stageX(0);
        cp_wait0(); __syncthreads();
        if (s == 0) {
#pragma unroll
            for (int hh = 0; hh < 2; hh++) {
                int m = hh ? em1 : em0;
                const float* xm = &XSf[m * 36];
                float gi0 = xm[     cc*2], gi1 = xm[     cc*2 + 1];
                float gg0 = xm[16 + cc*2], gg1 = xm[16 + cc*2 + 1];
                float go0 = xm[24 + cc*2], go1 = xm[24 + cc*2 + 1];
                float cn0 = fsig(gi0) * ftanh_(gg0);
                float cn1 = fsig(gi1) * ftanh_(gg1);
                c1v[hh] = make_float2(cn0, cn1);
                float h0 = fsig(go0) * ftanh_(cn0);
                float h1 = fsig(go1) * ftanh_(cn1);
                HRf[m * 10 + cc * 2]     = h0;
                HRf[m * 10 + cc * 2 + 1] = h1;
                g_h1p[1][((((bx >> 1) * 4 + mt) * 32 + lane) * 4)
                         + hh + 2 * (bx & 1)] = pk(h0, h1);
            }
        }
        gbar(NCTA);
    }

    for (int t = 0; t < NT - 1; t++) {
        const uint4* Aw1 = (const uint4*)(g_h1p[(t + 1) & 1]) + (s * 32) * 128 + fragoff;
        const uint4* Aw2 = (const uint4*)(g_h2p[t & 1])       + (s * 32) * 128 + fragoff;
        float accL2[4][4] = {};
        float accL1[4][4] = {};

        stageX(t + 1);

        uint4 ring[8];
#pragma unroll
        for (int p = 0; p < 8; p++) ring[p] = __ldcg(Aw1 + p * 128);
#pragma unroll 8
        for (int i = 0; i < 32; i++) {
            uint4 a = ring[i & 7];
            int r = i + 8;
            ring[i & 7] = (r < 32) ? __ldcg(Aw1 + r * 128)
                                   : __ldcg(Aw2 + (r - 32) * 128);
            const int kc = s * 32 + i;
#pragma unroll
            for (int g = 0; g < 4; g++)
                mmabf(accL2[g], a, Wsm2[(kc * 4 + g) * 32 + lane]);
#pragma unroll
            for (int g = 0; g < 4; g++)
                mmabf(accL1[g], a, Wsm1[(kc * 4 + g) * 32 + lane]);
        }
#pragma unroll 8
        for (int i = 0; i < 32; i++) {
            uint4 a = ring[i & 7];
            if (i + 8 < 32) ring[i & 7] = __ldcg(Aw2 + (i + 8) * 128);
            const int kc = 64 + s * 32 + i;
#pragma unroll
            for (int g = 0; g < 4; g++)
                mmabf(accL2[g], a, Wsm2[(kc * 4 + g) * 32 + lane]);
        }

        if (s == 0) {
#pragma unroll
            for (int g = 0; g < 4; g++) {
                Gs [em0 * 36 + g * 8 + cc * 2]     = accL2[g][0];
                Gs [em0 * 36 + g * 8 + cc * 2 + 1] = accL2[g][1];
                Gs [em1 * 36 + g * 8 + cc * 2]     = accL2[g][2];
                Gs [em1 * 36 + g * 8 + cc * 2 + 1] = accL2[g][3];
            }
        } else {
#pragma unroll
            for (int g = 0; g < 4; g++) {
                Gs2[em0 * 36 + g * 8 + cc * 2]     = accL1[g][0];
                Gs2[em0 * 36 + g * 8 + cc * 2 + 1] = accL1[g][1];
                Gs2[em1 * 36 + g * 8 + cc * 2]     = accL1[g][2];
                Gs2[em1 * 36 + g * 8 + cc * 2 + 1] = accL1[g][3];
            }
        }
        cp_wait0();
        __syncthreads();
        if (s == 1) {
            const float* hr = &HRf[(t & 1) * 640];
#pragma unroll
            for (int hh = 0; hh < 2; hh++) {
                int m = hh ? em1 : em0;
                float gi0 = accL2[0][hh*2]   + Gs[m*36 +      cc*2]     + b2i.x;
                float gi1 = accL2[0][hh*2+1] + Gs[m*36 +      cc*2 + 1] + b2i.y;
                float gf0 = accL2[1][hh*2]   + Gs[m*36 +  8 + cc*2]     + b2f.x;
                float gf1 = accL2[1][hh*2+1] + Gs[m*36 +  8 + cc*2 + 1] + b2f.y;
                float gg0 = accL2[2][hh*2]   + Gs[m*36 + 16 + cc*2]     + b2g.x;
                float gg1 = accL2[2][hh*2+1] + Gs[m*36 + 16 + cc*2 + 1] + b2g.y;
                float go0 = accL2[3][hh*2]   + Gs[m*36 + 24 + cc*2]     + b2o.x;
                float go1 = accL2[3][hh*2+1] + Gs[m*36 + 24 + cc*2 + 1] + b2o.y;
                float cn0 = fsig(gf0) * c2v[hh].x + fsig(gi0) * ftanh_(gg0);
                float cn1 = fsig(gf1) * c2v[hh].y + fsig(gi1) * ftanh_(gg1);
                c2v[hh] = make_float2(cn0, cn1);
                float h0 = fsig(go0) * ftanh_(cn0);
                float h1 = fsig(go1) * ftanh_(cn1);
                g_h2p[(t + 1) & 1][((((bx >> 1) * 4 + mt) * 32 + lane) * 4)
                                   + hh + 2 * (bx & 1)] = pk(h0, h1);
                float r0 = hr[m * 10 + cc * 2], r1 = hr[m * 10 + cc * 2 + 1];
                int mbL   = m * 2 + (t >> 6);
                int kcL   = bx >> 1;
                int mtL   = (t >> 4) & 3;
                int laneL = (t & 7) * 4 + cc;
                int regL  = ((t >> 3) & 1) + 2 * (bx & 1);
                g_LOp[((((size_t)mbL * 64 + kcL) * 4 + mtL) * 32 + laneL) * 4 + regL]
                    = pk(h0 + r0, h1 + r1);
            }
        } else {
            float* hr = &HRf[((t + 1) & 1) * 640];
#pragma unroll
            for (int hh = 0; hh < 2; hh++) {
                int m = hh ? em1 : em0;
                const float* xm = &XSf[m * 36];
                float gi0 = accL1[0][hh*2]   + Gs2[m*36 +      cc*2]     + xm[     cc*2];
                float gi1 = accL1[0][hh*2+1] + Gs2[m*36 +      cc*2 + 1] + xm[     cc*2 + 1];
                float gf0 = accL1[1][hh*2]   + Gs2[m*36 +  8 + cc*2]     + xm[ 8 + cc*2];
                float gf1 = accL1[1][hh*2+1] + Gs2[m*36 +  8 + cc*2 + 1] + xm[ 8 + cc*2 + 1];
                float gg0 = accL1[2][hh*2]   + Gs2[m*36 + 16 + cc*2]     + xm[16 + cc*2];
                float gg1 = accL1[2][hh*2+1] + Gs2[m*36 + 16 + cc*2 + 1] + xm[16 + cc*2 + 1];
                float go0 = accL1[3][hh*2]   + Gs2[m*36 + 24 + cc*2]     + xm[24 + cc*2];
                float go1 = accL1[3][hh*2+1] + Gs2[m*36 + 24 + cc*2 + 1] + xm[24 + cc*2 + 1];
                float cn0 = fsig(gf0) * c1v[hh].x + fsig(gi0) * ftanh_(gg0);
                float cn1 = fsig(gf1) * c1v[hh].y + fsig(gi1) * ftanh_(gg1);
                c1v[hh] = make_float2(cn0, cn1);
                float h0 = fsig(go0) * ftanh_(cn0);
                float h1 = fsig(go1) * ftanh_(cn1);
                hr[m * 10 + cc * 2]     = h0;
                hr[m * 10 + cc * 2 + 1] = h1;
                g_h1p[(t + 2) & 1][((((bx >> 1) * 4 + mt) * 32 + lane) * 4)
                                   + hh + 2 * (bx & 1)] = pk(h0, h1);
            }
        }
        gbar((unsigned)(t + 2) * NCTA);
    }

    // tail: L2(127)
    {
        const int t = NT - 1;
        const uint4* Aw1 = (const uint4*)(g_h1p[(t + 1) & 1]) + (s * 32) * 128 + fragoff;
        const uint4* Aw2 = (const uint4*)(g_h2p[t & 1])       + (s * 32) * 128 + fragoff;
        float accL2[4][4] = {};
        uint4 ring[8];
#pragma unroll
        for (int p = 0; p < 8; p++) ring[p] = __ldcg(Aw1 + p * 128);
#pragma unroll 8
        for (int i = 0; i < 32; i++) {
            uint4 a = ring[i & 7];
            int r = i + 8;
            ring[i & 7] = (r < 32) ? __ldcg(Aw1 + r * 128)
                                   : __ldcg(Aw2 + (r - 32) * 128);
            const int kc = s * 32 + i;
#pragma unroll
            for (int g = 0; g < 4; g++)
                mmabf(accL2[g], a, Wsm2[(kc * 4 + g) * 32 + lane]);
        }
#pragma unroll 8
        for (int i = 0; i < 32; i++) {
            uint4 a = ring[i & 7];
            if (i + 8 < 32) ring[i & 7] = __ldcg(Aw2 + (i + 8) * 128);
            const int kc = 64 + s * 32 + i;
#pragma unroll
            for (int g = 0; g < 4; g++)
                mmabf(accL2[g], a, Wsm2[(kc * 4 + g) * 32 + lane]);
        }
        if (s == 0) {
#pragma unroll
            for (int g = 0; g < 4; g++) {
                Gs[em0 * 36 + g * 8 + cc * 2]     = accL2[g][0];
                Gs[em0 * 36 + g * 8 + cc * 2 + 1] = accL2[g][1];
                Gs[em1 * 36 + g * 8 + cc * 2]     = accL2[g][2];
                Gs[em1 * 36 + g * 8 + cc * 2 + 1] = accL2[g][3];
            }
        }
        __syncthreads();
        if (s == 1) {
            const float* hr = &HRf[(t & 1) * 640];
#pragma unroll
            for (int hh = 0; hh < 2; hh++) {
                int m = hh ? em1 : em0;
                float gi0 = accL2[0][hh*2]   + Gs[m*36 +      cc*2]     + b2i.x;
                float gi1 = accL2[0][hh*2+1] + Gs[m*36 +      cc*2 + 1] + b2i.y;
                float gf0 = accL2[1][hh*2]   + Gs[m*36 +  8 + cc*2]     + b2f.x;
                float gf1 = accL2[1][hh*2+1] + Gs[m*36 +  8 + cc*2 + 1] + b2f.y;
                float gg0 = accL2[2][hh*2]   + Gs[m*36 + 16 + cc*2]     + b2g.x;
                float gg1 = accL2[2][hh*2+1] + Gs[m*36 + 16 + cc*2 + 1] + b2g.y;
                float go0 = accL2[3][hh*2]   + Gs[m*36 + 24 + cc*2]     + b2o.x;
                float go1 = accL2[3][hh*2+1] + Gs[m*36 + 24 + cc*2 + 1] + b2o.y;
                float cn0 = fsig(gf0) * c2v[hh].x + fsig(gi0) * ftanh_(gg0);
                float cn1 = fsig(gf1) * c2v[hh].y + fsig(gi1) * ftanh_(gg1);
                float h0 = fsig(go0) * ftanh_(cn0);
                float h1 = fsig(go1) * ftanh_(cn1);
                float r0 = hr[m * 10 + cc * 2], r1 = hr[m * 10 + cc * 2 + 1];
                int mbL   = m * 2 + (t >> 6);
                int kcL   = bx >> 1;
                int mtL   = (t >> 4) & 3;
                int laneL = (t & 7) * 4 + cc;
                int regL  = ((t >> 3) & 1) + 2 * (bx & 1);
                g_LOp[((((size_t)mbL * 64 + kcL) * 4 + mtL) * 32 + laneL) * 4 + regL]
                    = pk(h0 + r0, h1 + r1);
            }
        }
    }
}

// =================== head GEMM 1: hid = relu(LO @ Wp1 + bp1) =================
__global__ __launch_bounds__(256) void k_mlp1b(const float* __restrict__ bp1)
{
    extern __shared__ uint4 sm[];
    const int tid = threadIdx.x, wid = tid >> 5, lane = tid & 31;
    const int mt = wid & 3, s = wid >> 2;
    const int rr = lane >> 2, cc = lane & 3;
    const int nb = blockIdx.x, mb = blockIdx.y;
    float acc[4][4] = {};
    const uint4* A4 = (const uint4*)g_LOp + (size_t)mb * 64 * 128;
    const uint4* B4 = (const uint4*)g_Wp1p + (size_t)nb * 64 * 128;

    auto loadst = [&](int it) {
        if (it < 16) {
            uint4* dst = sm + (it & 3) * 1024;
            const uint4* a = A4 + (size_t)it * 512;
            const uint4* b = B4 + (size_t)it * 512;
            cp16(&dst[tid],             &a[tid]);
            cp16(&dst[tid + 256],       &a[tid + 256]);
            cp16(&dst[512 + tid],       &b[tid]);
            cp16(&dst[512 + tid + 256], &b[tid + 256]);
        }
        cp_commit();
    };
    loadst(0); loadst(1); loadst(2);
    for (int it = 0; it < 16; it++) {
        cp_wait2(); __syncthreads();
        loadst(it + 3);
        const uint4* SA = sm + (it & 3) * 1024;
        const uint2* SB = (const uint2*)(SA + 512);
#pragma unroll
        for (int kcl = 0; kcl < 4; kcl++) {
            uint4 a = SA[(kcl * 4 + mt) * 32 + lane];
#pragma unroll
            for (int jn = 0; jn < 4; jn++) {
                uint2 b = SB[(kcl * 8 + s * 4 + jn) * 32 + lane];
                mmabf(acc[jn], a, b);
            }
        }
    }
#pragma unroll
    for (int jn = 0; jn < 4; jn++) {
        int c8  = s * 4 + jn;
        int col = nb * 64 + c8 * 8 + cc * 2;
        float b0 = bp1[col], b1 = bp1[col + 1];
        int kcH = nb * 4 + (c8 >> 1);
        int regH_base = 2 * (c8 & 1);
#pragma unroll
        for (int hh = 0; hh < 2; hh++) {
            float v0 = fmaxf(acc[jn][hh * 2 + 0] + b0, 0.f);
            float v1 = fmaxf(acc[jn][hh * 2 + 1] + b1, 0.f);
            g_HIDp[((((size_t)mb * 16 + kcH) * 4 + mt) * 32 + (rr * 4 + cc)) * 4
                   + hh + regH_base] = pk(v0, v1);
        }
    }
}

// =================== head GEMM 2: logits = hid @ Wp2 + bp2 ===================
__global__ __launch_bounds__(256) void k_logitsb(const float* __restrict__ bp2,
                                                 float* __restrict__ out)
{
    extern __shared__ uint4 sm[];
    const int tid = threadIdx.x, wid = tid >> 5, lane = tid & 31;
    const int mt = wid & 3, s = wid >> 2;
    const int rr = lane >> 2, cc = lane & 3;
    const int nb = blockIdx.x, mb = blockIdx.y;
    float acc[4][4] = {};
    const uint4* A4 = (const uint4*)g_HIDp + (size_t)mb * 16 * 128;
    const uint4* B4 = (const uint4*)g_Wp2p + (size_t)nb * 16 * 128;

    auto loadst = [&](int it) {
        if (it < 4) {
            uint4* dst = sm + (it & 3) * 1024;
            const uint4* a = A4 + (size_t)it * 512;
            const uint4* b = B4 + (size_t)it * 512;
            cp16(&dst[tid],             &a[tid]);
            cp16(&dst[tid + 256],       &a[tid + 256]);
            cp16(&dst[512 + tid],       &b[tid]);
            cp16(&dst[512 + tid + 256], &b[tid + 256]);
        }
        cp_commit();
    };
    loadst(0); loadst(1); loadst(2);
    for (int it = 0; it < 4; it++) {
        cp_wait2(); __syncthreads();
        loadst(it + 3);
        const uint4* SA = sm + (it & 3) * 1024;
        const uint2* SB = (const uint2*)(SA + 512);
#pragma unroll
        for (int kcl = 0; kcl < 4; kcl++) {
            uint4 a = SA[(kcl * 4 + mt) * 32 + lane];
#pragma unroll
            for (int jn = 0; jn < 4; jn++) {
                uint2 b = SB[(kcl * 8 + s * 4 + jn) * 32 + lane];
                mmabf(acc[jn], a, b);
            }
        }
    }
#pragma unroll
    for (int jn = 0; jn < 4; jn++) {
        int n = nb * 64 + (s * 4 + jn) * 8 + cc * 2;
        if (n < NANS) {
            float b0 = bp2[n], b1 = bp2[n + 1];
#pragma unroll
            for (int hh = 0; hh < 2; hh++) {
                int m = mb * 64 + mt * 16 + rr + hh * 8;
                float* o = out + (size_t)m * NANS + n;
                o[0] = acc[jn][hh * 2 + 0] + b0;
                o[1] = acc[jn][hh * 2 + 1] + b1;
            }
        }
    }
}

// ---------------- softmax ------------------------------------------------------
__global__ __launch_bounds__(256) void k_softmax(float* __restrict__ out)
{
    __shared__ float red[256];
    const int tid = threadIdx.x;
    float* p = out + (size_t)blockIdx.x * NANS;
    float v[4];
    float mx = -1e30f;
#pragma unroll
    for (int i = 0; i < 4; i++) {
        int n = tid + i * 256;
        v[i] = (n < NANS) ? p[n] : -1e30f;
        mx = fmaxf(mx, v[i]);
    }
    red[tid] = mx; __syncthreads();
    for (int s = 128; s > 0; s >>= 1) {
        if (tid < s) red[tid] = fmaxf(red[tid], red[tid + s]);
        __syncthreads();
    }
    mx = red[0]; __syncthreads();
    float sum = 0.f;
#pragma unroll
    for (int i = 0; i < 4; i++) {
        int n = tid + i * 256;
        if (n < NANS) { v[i] = expf(v[i] - mx); sum += v[i]; }
    }
    red[tid] = sum; __syncthreads();
    for (int s = 128; s > 0; s >>= 1) {
        if (tid < s) red[tid] += red[tid + s];
        __syncthreads();
    }
    float inv = 1.f / red[0];
#pragma unroll
    for (int i = 0; i < 4; i++) {
        int n = tid + i * 256;
        if (n < NANS) p[n] = v[i] * inv;
    }
}

// ---------------- launch ------------------------------------------------------
extern "C" void kernel_launch(void* const* d_in, const int* in_sizes, int n_in,
                              void* d_out, int out_size)
{
    const float* data1 = (const float*)d_in[0];
    const float* data2 = (const float*)d_in[1];
    const float* W_ih1 = (const float*)d_in[2];
    const float* W_hh1 = (const float*)d_in[3];
    const float* b1    = (const float*)d_in[4];
    const float* W_ih2 = (const float*)d_in[5];
    const float* W_hh2 = (const float*)d_in[6];
    const float* b2    = (const float*)d_in[7];
    const float* Wp1   = (const float*)d_in[8];
    const float* bp1   = (const float*)d_in[9];
    const float* Wp2   = (const float*)d_in[10];
    const float* bp2   = (const float*)d_in[11];
    float* out = (float*)d_out;

    static bool attr_done = false;
    if (!attr_done) {
        cudaFuncSetAttribute(k_xprojb,  cudaFuncAttributeMaxDynamicSharedMemorySize, 196608);
        cudaFuncSetAttribute(k_mlp1b,   cudaFuncAttributeMaxDynamicSharedMemorySize, 65536);
        cudaFuncSetAttribute(k_logitsb, cudaFuncAttributeMaxDynamicSharedMemorySize, 65536);
        cudaFuncSetAttribute(k_recur,   cudaFuncAttributeMaxDynamicSharedMemorySize, 229376);
        attr_done = true;
    }

    k_init_state<<<128, 256>>>();
    k_pack_all<<<dim3(1024, 6), 256>>>(W_hh1, W_ih2, W_hh2, data1, data2,
                                       W_ih1, Wp1, Wp2);
    k_xprojb<<<dim3(16, 64), 256, 196608>>>(b1);
    k_recur<<<128, 256, 229376>>>(b2);
    k_mlp1b<<<dim3(4, 128), 256, 65536>>>(bp1);
    k_logitsb<<<dim3(16, 128), 256, 65536>>>(bp2, out);
    k_softmax<<<BT, 256>>>(out);
}

// round 17
// speedup vs baseline: 1.0047x; 1.0047x over previous
#include <cuda_runtime.h>
#include <cuda_bf16.h>
#include <cstdint>
#include <math.h>

#define NB   64
#define NT   128
#define BT   8192
#define H    1024
#define DIN  2048
#define G4   4096
#define NH1  256
#define NANS 1000
#define NCTA 128u

// ---------------- device scratch ----------------
__device__ __align__(16) uint32_t g_X1b[(size_t)BT * 2048]; // [t][b][4H] bf16 pairs (incl +b1)
__device__ unsigned g_bar;
// h in bf16 A-fragment layout: [kc(64)][mt(4)][lane(32)][reg(4)] u32
__device__ __align__(16) uint32_t g_h1p[2][32768];
__device__ __align__(16) uint32_t g_h2p[2][32768];
// step weights, B-fragment layout: [bx(128)][kc][g(4)][lane(32)] uint2
__device__ __align__(16) uint32_t g_W1p[128 * 64 * 4 * 32 * 2];     // 8 MB
__device__ __align__(16) uint32_t g_W2p[128 * 128 * 4 * 32 * 2];    // 16 MB
// xproj operands (fragment-packed)
__device__ __align__(16) uint32_t g_Ax[(size_t)128 * 128 * 4 * 32 * 4];  // 32 MB
__device__ __align__(16) uint32_t g_Wx[(size_t)64 * 128 * 8 * 32 * 2];   // 16 MB
// head: lstm_out bf16 A-frag [mb(128)][kc(64)][mt(4)][lane(32)][reg(4)]
__device__ __align__(16) uint32_t g_LOp[(size_t)128 * 64 * 4 * 32 * 4];  // 16 MB
// hid bf16 A-frag [mb(128)][kc(16)][mt][lane][reg]
__device__ __align__(16) uint32_t g_HIDp[(size_t)128 * 16 * 4 * 32 * 4]; // 4 MB
__device__ __align__(16) uint32_t g_Wp1p[4 * 64 * 8 * 32 * 2];
__device__ __align__(16) uint32_t g_Wp2p[16 * 16 * 8 * 32 * 2];

// fast activations
__device__ __forceinline__ float fsig(float x) {
    return __fdividef(1.f, 1.f + __expf(-x));
}
__device__ __forceinline__ float ftanh_(float x) {
    return fmaf(2.f, fsig(2.f * x), -1.f);
}
__device__ __forceinline__ uint32_t pk(float x, float y) {
    __nv_bfloat162 v = __floats2bfloat162_rn(x, y);
    return *reinterpret_cast<uint32_t*>(&v);
}
__device__ __forceinline__ float2 bf2f(uint32_t u) {
    __nv_bfloat162 v = *reinterpret_cast<__nv_bfloat162*>(&u);
    return __bfloat1622float2(v);
}
__device__ __forceinline__ void mmabf(float c[4], uint4 a, uint2 b) {
    asm volatile(
        "mma.sync.aligned.m16n8k16.row.col.f32.bf16.bf16.f32 "
        "{%0,%1,%2,%3},{%4,%5,%6,%7},{%8,%9},{%0,%1,%2,%3};"
        : "+f"(c[0]), "+f"(c[1]), "+f"(c[2]), "+f"(c[3])
        : "r"(a.x), "r"(a.y), "r"(a.z), "r"(a.w), "r"(b.x), "r"(b.y));
}
__device__ __forceinline__ void cp16(void* smem, const void* g) {
    uint32_t s = (uint32_t)__cvta_generic_to_shared(smem);
    asm volatile("cp.async.cg.shared.global [%0], [%1], 16;" :: "r"(s), "l"(g));
}
__device__ __forceinline__ void cp_commit() { asm volatile("cp.async.commit_group;"); }
__device__ __forceinline__ void cp_wait2()  { asm volatile("cp.async.wait_group 2;"); }
__device__ __forceinline__ void cp_wait0()  { asm volatile("cp.async.wait_group 0;"); }

// ---------------- init ----------------
__global__ void k_init_state() {
    int i = blockIdx.x * blockDim.x + threadIdx.x;
    if (i == 0) g_bar = 0u;
    if (i < 32768) { g_h1p[0][i] = 0u; g_h2p[0][i] = 0u; }
}

// ---------------- unified pack kernel (job = blockIdx.y) ---------------------
__global__ void k_pack_all(
    const float* __restrict__ W_hh1, const float* __restrict__ W_ih2,
    const float* __restrict__ W_hh2, const float* __restrict__ d1,
    const float* __restrict__ d2,   const float* __restrict__ W_ih1,
    const float* __restrict__ Wp1,  const float* __restrict__ Wp2)
{
    const int job = blockIdx.y;
    const int gid = blockIdx.x * blockDim.x + threadIdx.x;
    const int stride = gridDim.x * blockDim.x;

    if (job == 0) {
        uint2* out = (uint2*)g_W1p;
        for (int idx = gid; idx < 128 * 64 * 4 * 32; idx += stride) {
            int lane = idx & 31;
            int t1 = idx >> 5;  int g = t1 & 3;
            int t2 = t1 >> 2;   int kc = t2 & 63; int bx = t2 >> 6;
            int rr = lane >> 2, cc = lane & 3;
            const float* p = W_hh1 + (size_t)(g * H + bx * 8 + rr) * H + kc * 16 + cc * 2;
            uint2 v; v.x = pk(p[0], p[1]); v.y = pk(p[8], p[9]);
            out[idx] = v;
        }
    } else if (job == 1) {
        uint2* out = (uint2*)g_W2p;
        for (int idx = gid; idx < 128 * 128 * 4 * 32; idx += stride) {
            int lane = idx & 31;
            int t1 = idx >> 5;  int g = t1 & 3;
            int t2 = t1 >> 2;   int kc = t2 & 127; int bx = t2 >> 7;
            int rr = lane >> 2, cc = lane & 3;
            int row = g * H + bx * 8 + rr;
            const float* W = W_ih2; int k0 = kc * 16 + cc * 2;
            if (kc >= 64) { W = W_hh2; k0 -= 1024; }
            const float* p = W + (size_t)row * H + k0;
            uint2 v; v.x = pk(p[0], p[1]); v.y = pk(p[8], p[9]);
            out[idx] = v;
        }
    } else if (job == 2) {
        uint4* out = (uint4*)g_Ax;
        for (int idx = gid; idx < 128 * 128 * 4 * 32; idx += stride) {
            int lane = idx & 31;
            int t1 = idx >> 5;
            int mt = t1 & 3; t1 >>= 2;
            int kc = t1 & 127;
            int mb = t1 >> 7;
            int rr = lane >> 2, cc = lane & 3;
            int r0 = mb * 64 + mt * 16 + rr, r1 = r0 + 8;
            int k0 = kc * 16 + cc * 2;
            const float *s0, *s1;
            if (k0 < 1024) { s0 = d1 + (size_t)r0 * 1024 + k0;        s1 = d1 + (size_t)r1 * 1024 + k0; }
            else           { s0 = d2 + (size_t)r0 * 1024 + k0 - 1024; s1 = d2 + (size_t)r1 * 1024 + k0 - 1024; }
            uint4 v;
            v.x = pk(s0[0], s0[1]);
            v.y = pk(s1[0], s1[1]);
            v.z = pk(s0[8], s0[9]);
            v.w = pk(s1[8], s1[9]);
            out[idx] = v;
        }
    } else if (job == 3) {
        uint2* out = (uint2*)g_Wx;
        for (int idx = gid; idx < 64 * 128 * 8 * 32; idx += stride) {
            int lane = idx & 31;
            int t1 = idx >> 5;
            int c = t1 & 7; t1 >>= 3;
            int kc = t1 & 127;
            int nb = t1 >> 7;
            int rr = lane >> 2, cc = lane & 3;
            const float* p = W_ih1 + (size_t)(nb * 64 + c * 8 + rr) * DIN + kc * 16 + cc * 2;
            uint2 v; v.x = pk(p[0], p[1]); v.y = pk(p[8], p[9]);
            out[idx] = v;
        }
    } else if (job == 4) {
        uint2* out = (uint2*)g_Wp1p;
        for (int idx = gid; idx < 4 * 64 * 8 * 32; idx += stride) {
            int lane = idx & 31;
            int t1 = idx >> 5;
            int c = t1 & 7; t1 >>= 3;
            int kc = t1 & 63;
            int nb = t1 >> 6;
            int rr = lane >> 2, cc = lane & 3;
            int n  = nb * 64 + c * 8 + rr;
            int k0 = kc * 16 + cc * 2;
            uint2 v;
            v.x = pk(Wp1[(size_t)k0 * NH1 + n],       Wp1[(size_t)(k0 + 1) * NH1 + n]);
            v.y = pk(Wp1[(size_t)(k0 + 8) * NH1 + n], Wp1[(size_t)(k0 + 9) * NH1 + n]);
            out[idx] = v;
        }
    } else {
        uint2* out = (uint2*)g_Wp2p;
        for (int idx = gid; idx < 16 * 16 * 8 * 32; idx += stride) {
            int lane = idx & 31;
            int t1 = idx >> 5;
            int c = t1 & 7; t1 >>= 3;
            int kc = t1 & 15;
            int nb = t1 >> 4;
            int rr = lane >> 2, cc = lane & 3;
            int n  = nb * 64 + c * 8 + rr;
            int k0 = kc * 16 + cc * 2;
            float a0 = 0.f, a1 = 0.f, b0 = 0.f, b1 = 0.f;
            if (n < NANS) {
                a0 = Wp2[(size_t)k0 * NANS + n];       a1 = Wp2[(size_t)(k0 + 1) * NANS + n];
                b0 = Wp2[(size_t)(k0 + 8) * NANS + n]; b1 = Wp2[(size_t)(k0 + 9) * NANS + n];
            }
            uint2 v; v.x = pk(a0, a1); v.y = pk(b0, b1);
            out[idx] = v;
        }
    }
}

// =================== xproj: bf16 mma, 128x256 CTA tile (R12 core) ===========
// Output X1 now bf16-packed: halves epilogue store traffic.
__global__ __launch_bounds__(256) void k_xprojb(const float* __restrict__ bias)
{
    extern __shared__ uint4 sm[];
    const int tid = threadIdx.x, wid = tid >> 5, lane = tid & 31;
    const int mt = wid & 3, s = wid >> 2;
    const int rr = lane >> 2, cc = lane & 3;
    const int nb = blockIdx.x, mb = blockIdx.y;
    float acc[2][16][4] = {};
    const uint4* Abase = (const uint4*)g_Ax + (size_t)(mb * 2) * 16384;
    const uint4* Bbase = (const uint4*)g_Wx + (size_t)(nb * 4) * 16384;

    auto loadst = [&](int it) {
        if (it < 32) {
            uint4* dst = sm + (it & 3) * 3072;
            const int kc0 = it * 4;
#pragma unroll
            for (int e = 0; e < 12; e++) {
                int flat = e * 256 + tid;
                const uint4* src;
                if (flat < 1024) {
                    int q = flat >> 7, i = flat & 127;
                    int h = q >> 2, kcl = q & 3;
                    src = Abase + (size_t)h * 16384 + (kc0 + kcl) * 128 + i;
                } else {
                    int f2 = flat - 1024;
                    int q = f2 >> 7, i = f2 & 127;
                    int cb = q >> 2, kcl = q & 3;
                    src = Bbase + (size_t)cb * 16384 + (kc0 + kcl) * 128 + i;
                }
                cp16(&dst[flat], src);
            }
        }
        cp_commit();
    };
    loadst(0); loadst(1); loadst(2);
    for (int it = 0; it < 32; it++) {
        cp_wait2(); __syncthreads();
        loadst(it + 3);
        const uint4* SA = sm + (it & 3) * 3072;
        const uint2* SB = (const uint2*)(SA + 1024);
#pragma unroll
        for (int kcl = 0; kcl < 4; kcl++) {
            uint4 a0 = SA[(kcl    ) * 128 + mt * 32 + lane];
            uint4 a1 = SA[(4 + kcl) * 128 + mt * 32 + lane];
#pragma unroll
            for (int cbl = 0; cbl < 2; cbl++) {
                int cb = s * 2 + cbl;
#pragma unroll
                for (int c = 0; c < 8; c++) {
                    uint2 b = SB[((cb * 4 + kcl) * 8 + c) * 32 + lane];
                    mmabf(acc[0][cbl * 8 + c], a0, b);
                    mmabf(acc[1][cbl * 8 + c], a1, b);
                }
            }
        }
    }
#pragma unroll
    for (int h = 0; h < 2; h++)
#pragma unroll
    for (int cg = 0; cg < 16; cg++) {
        int cb = s * 2 + (cg >> 3), c = cg & 7;
        int col = nb * 256 + cb * 64 + c * 8 + cc * 2;
        float b0 = bias[col], b1 = bias[col + 1];
#pragma unroll
        for (int hh = 0; hh < 2; hh++) {
            int m = mb * 128 + h * 64 + mt * 16 + rr + hh * 8;
            int tt = m & 127, bb = m >> 7;
            g_X1b[((size_t)tt * NB + bb) * 2048 + (col >> 1)]
                = pk(acc[h][cg][hh * 2 + 0] + b0, acc[h][cg][hh * 2 + 1] + b1);
        }
    }
}

// =================== persistent recurrence kernel ===========================
// R15 core + bf16 X slab + LOp store moved into the barrier window.
// smem (uint4): Gs[0,576) Gs2[576,1152) W1[1152,5248) W2[5248,13440)
//               XSu u32 @ [13440,13760) (64 rows x 20 u32)  HR @ [13760,14080)
__global__ __launch_bounds__(256) void k_recur(const float* __restrict__ b2)
{
    extern __shared__ uint4 sm[];
    const int tid = threadIdx.x, wid = tid >> 5, lane = tid & 31;
    const int mt = wid & 3, s = wid >> 2;
    const int rr = lane >> 2, cc = lane & 3;
    const int bx = blockIdx.x;
    float* Gs   = (float*)sm;
    float* Gs2  = (float*)(sm + 576);
    const uint2* Wsm1 = (const uint2*)(sm + 1152);
    const uint2* Wsm2 = (const uint2*)(sm + 5248);
    uint32_t* XSu = (uint32_t*)(sm + 13440);   // [64][20] u32 (bf16 pairs)
    float* HRf  = (float*)(sm + 13760);        // [2][64][10]
    const int j = bx * 8 + cc * 2;
    const int j0 = bx * 8;
    const int fragoff = mt * 32 + lane;

    {
        const uint4* w1 = (const uint4*)g_W1p + (size_t)bx * 4096;
        for (int i = tid; i < 4096; i += 256) cp16(&sm[1152 + i], &w1[i]);
        const uint4* w2 = (const uint4*)g_W2p + (size_t)bx * 8192;
        for (int i = tid; i < 8192; i += 256) cp16(&sm[5248 + i], &w2[i]);
        cp_commit(); cp_wait0(); __syncthreads();
    }

    float2 b2i = make_float2(b2[j],         b2[j + 1]);
    float2 b2f = make_float2(b2[H + j],     b2[H + j + 1]);
    float2 b2g = make_float2(b2[2 * H + j], b2[2 * H + j + 1]);
    float2 b2o = make_float2(b2[3 * H + j], b2[3 * H + j + 1]);

    const int em0 = mt * 16 + rr, em1 = em0 + 8;
    float2 c1v[2] = { make_float2(0.f, 0.f), make_float2(0.f, 0.f) };
    float2 c2v[2] = { make_float2(0.f, 0.f), make_float2(0.f, 0.f) };
    const int sm_m = tid >> 2, sm_g = tid & 3;   // stageX mapping

    auto stageX = [&](int tt) {
        const uint32_t* Xt = g_X1b + (size_t)tt * NB * 2048;
        cp16(&XSu[sm_m * 20 + sm_g * 4],
             Xt + (size_t)sm_m * 2048 + sm_g * 512 + (j0 >> 1));
        cp_commit();
    };

    // prologue: L1(0) = cell(X1[0]) by s==0
    {
        stageX(0);
        cp_wait0(); __syncthreads();
        if (s == 0) {
#pragma unroll
            for (int hh = 0; hh < 2; hh++) {
                int m = hh ? em1 : em0;
                const uint32_t* xm = &XSu[m * 20];
                float2 xi = bf2f(xm[      cc]);
                float2 xg = bf2f(xm[ 8  + cc]);
                float2 xo = bf2f(xm[ 12 + cc]);
                float cn0 = fsig(xi.x) * ftanh_(xg.x);
                float cn1 = fsig(xi.y) * ftanh_(xg.y);
                c1v[hh] = make_float2(cn0, cn1);
                float h0 = fsig(xo.x) * ftanh_(cn0);
                float h1 = fsig(xo.y) * ftanh_(cn1);
                HRf[m * 10 + cc * 2]     = h0;
                HRf[m * 10 + cc * 2 + 1] = h1;
                g_h1p[1][((((bx >> 1) * 4 + mt) * 32 + lane) * 4)
                         + hh + 2 * (bx & 1)] = pk(h0, h1);
            }
        }
        // gbar(NCTA)
        __syncthreads();
        if (tid == 0) {
            unsigned* bp = &g_bar;
            asm volatile("red.release.gpu.global.add.u32 [%0], %1;"
                         :: "l"(bp), "r"(1u) : "memory");
            unsigned v;
            do { asm volatile("ld.acquire.gpu.global.u32 %0, [%1];"
                              : "=r"(v) : "l"(bp) : "memory"); } while (v < NCTA);
        }
        __syncthreads();
    }

    for (int t = 0; t < NT - 1; t++) {
        const uint4* Aw1 = (const uint4*)(g_h1p[(t + 1) & 1]) + (s * 32) * 128 + fragoff;
        const uint4* Aw2 = (const uint4*)(g_h2p[t & 1])       + (s * 32) * 128 + fragoff;
        float accL2[4][4] = {};
        float accL1[4][4] = {};

        stageX(t + 1);

        uint4 ring[8];
#pragma unroll
        for (int p = 0; p < 8; p++) ring[p] = __ldcg(Aw1 + p * 128);
#pragma unroll 8
        for (int i = 0; i < 32; i++) {
            uint4 a = ring[i & 7];
            int r = i + 8;
            ring[i & 7] = (r < 32) ? __ldcg(Aw1 + r * 128)
                                   : __ldcg(Aw2 + (r - 32) * 128);
            const int kc = s * 32 + i;
#pragma unroll
            for (int g = 0; g < 4; g++)
                mmabf(accL2[g], a, Wsm2[(kc * 4 + g) * 32 + lane]);
#pragma unroll
            for (int g = 0; g < 4; g++)
                mmabf(accL1[g], a, Wsm1[(kc * 4 + g) * 32 + lane]);
        }
#pragma unroll 8
        for (int i = 0; i < 32; i++) {
            uint4 a = ring[i & 7];
            if (i + 8 < 32) ring[i & 7] = __ldcg(Aw2 + (i + 8) * 128);
            const int kc = 64 + s * 32 + i;
#pragma unroll
            for (int g = 0; g < 4; g++)
                mmabf(accL2[g], a, Wsm2[(kc * 4 + g) * 32 + lane]);
        }

        if (s == 0) {
#pragma unroll
            for (int g = 0; g < 4; g++) {
                Gs [em0 * 36 + g * 8 + cc * 2]     = accL2[g][0];
                Gs [em0 * 36 + g * 8 + cc * 2 + 1] = accL2[g][1];
                Gs [em1 * 36 + g * 8 + cc * 2]     = accL2[g][2];
                Gs [em1 * 36 + g * 8 + cc * 2 + 1] = accL2[g][3];
            }
        } else {
#pragma unroll
            for (int g = 0; g < 4; g++) {
                Gs2[em0 * 36 + g * 8 + cc * 2]     = accL1[g][0];
                Gs2[em0 * 36 + g * 8 + cc * 2 + 1] = accL1[g][1];
                Gs2[em1 * 36 + g * 8 + cc * 2]     = accL1[g][2];
                Gs2[em1 * 36 + g * 8 + cc * 2 + 1] = accL1[g][3];
            }
        }
        cp_wait0();
        __syncthreads();
        uint32_t loS[2];                     // LOp payload stash (s==1)
        if (s == 1) {
            const float* hr = &HRf[(t & 1) * 640];
#pragma unroll
            for (int hh = 0; hh < 2; hh++) {
                int m = hh ? em1 : em0;
                float gi0 = accL2[0][hh*2]   + Gs[m*36 +      cc*2]     + b2i.x;
                float gi1 = accL2[0][hh*2+1] + Gs[m*36 +      cc*2 + 1] + b2i.y;
                float gf0 = accL2[1][hh*2]   + Gs[m*36 +  8 + cc*2]     + b2f.x;
                float gf1 = accL2[1][hh*2+1] + Gs[m*36 +  8 + cc*2 + 1] + b2f.y;
                float gg0 = accL2[2][hh*2]   + Gs[m*36 + 16 + cc*2]     + b2g.x;
                float gg1 = accL2[2][hh*2+1] + Gs[m*36 + 16 + cc*2 + 1] + b2g.y;
                float go0 = accL2[3][hh*2]   + Gs[m*36 + 24 + cc*2]     + b2o.x;
                float go1 = accL2[3][hh*2+1] + Gs[m*36 + 24 + cc*2 + 1] + b2o.y;
                float cn0 = fsig(gf0) * c2v[hh].x + fsig(gi0) * ftanh_(gg0);
                float cn1 = fsig(gf1) * c2v[hh].y + fsig(gi1) * ftanh_(gg1);
                c2v[hh] = make_float2(cn0, cn1);
                float h0 = fsig(go0) * ftanh_(cn0);
                float h1 = fsig(go1) * ftanh_(cn1);
                g_h2p[(t + 1) & 1][((((bx >> 1) * 4 + mt) * 32 + lane) * 4)
                                   + hh + 2 * (bx & 1)] = pk(h0, h1);
                loS[hh] = pk(h0 + hr[m * 10 + cc * 2], h1 + hr[m * 10 + cc * 2 + 1]);
            }
        } else {
            float* hr = &HRf[((t + 1) & 1) * 640];
#pragma unroll
            for (int hh = 0; hh < 2; hh++) {
                int m = hh ? em1 : em0;
                const uint32_t* xm = &XSu[m * 20];
                float2 xi = bf2f(xm[      cc]);
                float2 xf = bf2f(xm[ 4  + cc]);
                float2 xg = bf2f(xm[ 8  + cc]);
                float2 xo = bf2f(xm[ 12 + cc]);
                float gi0 = accL1[0][hh*2]   + Gs2[m*36 +      cc*2]     + xi.x;
                float gi1 = accL1[0][hh*2+1] + Gs2[m*36 +      cc*2 + 1] + xi.y;
                float gf0 = accL1[1][hh*2]   + Gs2[m*36 +  8 + cc*2]     + xf.x;
                float gf1 = accL1[1][hh*2+1] + Gs2[m*36 +  8 + cc*2 + 1] + xf.y;
                float gg0 = accL1[2][hh*2]   + Gs2[m*36 + 16 + cc*2]     + xg.x;
                float gg1 = accL1[2][hh*2+1] + Gs2[m*36 + 16 + cc*2 + 1] + xg.y;
                float go0 = accL1[3][hh*2]   + Gs2[m*36 + 24 + cc*2]     + xo.x;
                float go1 = accL1[3][hh*2+1] + Gs2[m*36 + 24 + cc*2 + 1] + xo.y;
                float cn0 = fsig(gf0) * c1v[hh].x + fsig(gi0) * ftanh_(gg0);
                float cn1 = fsig(gf1) * c1v[hh].y + fsig(gi1) * ftanh_(gg1);
                c1v[hh] = make_float2(cn0, cn1);
                float h0 = fsig(go0) * ftanh_(cn0);
                float h1 = fsig(go1) * ftanh_(cn1);
                hr[m * 10 + cc * 2]     = h0;
                hr[m * 10 + cc * 2 + 1] = h1;
                g_h1p[(t + 2) & 1][((((bx >> 1) * 4 + mt) * 32 + lane) * 4)
                                   + hh + 2 * (bx & 1)] = pk(h0, h1);
            }
        }
        // --- barrier with LOp store overlapped into the wait window ---
        __syncthreads();
        if (tid == 0) {
            unsigned* bp = &g_bar;
            asm volatile("red.release.gpu.global.add.u32 [%0], %1;"
                         :: "l"(bp), "r"(1u) : "memory");
        }
        if (s == 1) {
            const int kcL   = bx >> 1;
            const int mtL   = (t >> 4) & 3;
            const int laneL = (t & 7) * 4 + cc;
            const int regL  = ((t >> 3) & 1) + 2 * (bx & 1);
#pragma unroll
            for (int hh = 0; hh < 2; hh++) {
                int m = hh ? em1 : em0;
                int mbL = m * 2 + (t >> 6);
                g_LOp[((((size_t)mbL * 64 + kcL) * 4 + mtL) * 32 + laneL) * 4 + regL]
                    = loS[hh];
            }
        }
        if (tid == 0) {
            unsigned v;
            unsigned* bp = &g_bar;
            do { asm volatile("ld.acquire.gpu.global.u32 %0, [%1];"
                              : "=r"(v) : "l"(bp) : "memory"); }
            while (v < (unsigned)(t + 2) * NCTA);
        }
        __syncthreads();
    }

    // tail: L2(127)
    {
        const int t = NT - 1;
        const uint4* Aw1 = (const uint4*)(g_h1p[(t + 1) & 1]) + (s * 32) * 128 + fragoff;
        const uint4* Aw2 = (const uint4*)(g_h2p[t & 1])       + (s * 32) * 128 + fragoff;
        float accL2[4][4] = {};
        uint4 ring[8];
#pragma unroll
        for (int p = 0; p < 8; p++) ring[p] = __ldcg(Aw1 + p * 128);
#pragma unroll 8
        for (int i = 0; i < 32; i++) {
            uint4 a = ring[i & 7];
            int r = i + 8;
            ring[i & 7] = (r < 32) ? __ldcg(Aw1 + r * 128)
                                   : __ldcg(Aw2 + (r - 32) * 128);
            const int kc = s * 32 + i;
#pragma unroll
            for (int g = 0; g < 4; g++)
                mmabf(accL2[g], a, Wsm2[(kc * 4 + g) * 32 + lane]);
        }
#pragma unroll 8
        for (int i = 0; i < 32; i++) {
            uint4 a = ring[i & 7];
            if (i + 8 < 32) ring[i & 7] = __ldcg(Aw2 + (i + 8) * 128);
            const int kc = 64 + s * 32 + i;
#pragma unroll
            for (int g = 0; g < 4; g++)
                mmabf(accL2[g], a, Wsm2[(kc * 4 + g) * 32 + lane]);
        }
        if (s == 0) {
#pragma unroll
            for (int g = 0; g < 4; g++) {
                Gs[em0 * 36 + g * 8 + cc * 2]     = accL2[g][0];
                Gs[em0 * 36 + g * 8 + cc * 2 + 1] = accL2[g][1];
                Gs[em1 * 36 + g * 8 + cc * 2]     = accL2[g][2];
                Gs[em1 * 36 + g * 8 + cc * 2 + 1] = accL2[g][3];
            }
        }
        __syncthreads();
        if (s == 1) {
            const float* hr = &HRf[(t & 1) * 640];
#pragma unroll
            for (int hh = 0; hh < 2; hh++) {
                int m = hh ? em1 : em0;
                float gi0 = accL2[0][hh*2]   + Gs[m*36 +      cc*2]     + b2i.x;
                float gi1 = accL2[0][hh*2+1] + Gs[m*36 +      cc*2 + 1] + b2i.y;
                float gf0 = accL2[1][hh*2]   + Gs[m*36 +  8 + cc*2]     + b2f.x;
                float gf1 = accL2[1][hh*2+1] + Gs[m*36 +  8 + cc*2 + 1] + b2f.y;
                float gg0 = accL2[2][hh*2]   + Gs[m*36 + 16 + cc*2]     + b2g.x;
                float gg1 = accL2[2][hh*2+1] + Gs[m*36 + 16 + cc*2 + 1] + b2g.y;
                float go0 = accL2[3][hh*2]   + Gs[m*36 + 24 + cc*2]     + b2o.x;
                float go1 = accL2[3][hh*2+1] + Gs[m*36 + 24 + cc*2 + 1] + b2o.y;
                float cn0 = fsig(gf0) * c2v[hh].x + fsig(gi0) * ftanh_(gg0);
                float cn1 = fsig(gf1) * c2v[hh].y + fsig(gi1) * ftanh_(gg1);
                float h0 = fsig(go0) * ftanh_(cn0);
                float h1 = fsig(go1) * ftanh_(cn1);
                float r0 = hr[m * 10 + cc * 2], r1 = hr[m * 10 + cc * 2 + 1];
                int mbL   = m * 2 + (t >> 6);
                int kcL   = bx >> 1;
                int mtL   = (t >> 4) & 3;
                int laneL = (t & 7) * 4 + cc;
                int regL  = ((t >> 3) & 1) + 2 * (bx & 1);
                g_LOp[((((size_t)mbL * 64 + kcL) * 4 + mtL) * 32 + laneL) * 4 + regL]
                    = pk(h0 + r0, h1 + r1);
            }
        }
    }
}

// =================== head GEMM 1: hid = relu(LO @ Wp1 + bp1) =================
__global__ __launch_bounds__(256) void k_mlp1b(const float* __restrict__ bp1)
{
    extern __shared__ uint4 sm[];
    const int tid = threadIdx.x, wid = tid >> 5, lane = tid & 31;
    const int mt = wid & 3, s = wid >> 2;
    const int rr = lane >> 2, cc = lane & 3;
    const int nb = blockIdx.x, mb = blockIdx.y;
    float acc[4][4] = {};
    const uint4* A4 = (const uint4*)g_LOp + (size_t)mb * 64 * 128;
    const uint4* B4 = (const uint4*)g_Wp1p + (size_t)nb * 64 * 128;

    auto loadst = [&](int it) {
        if (it < 16) {
            uint4* dst = sm + (it & 3) * 1024;
            const uint4* a = A4 + (size_t)it * 512;
            const uint4* b = B4 + (size_t)it * 512;
            cp16(&dst[tid],             &a[tid]);
            cp16(&dst[tid + 256],       &a[tid + 256]);
            cp16(&dst[512 + tid],       &b[tid]);
            cp16(&dst[512 + tid + 256], &b[tid + 256]);
        }
        cp_commit();
    };
    loadst(0); loadst(1); loadst(2);
    for (int it = 0; it < 16; it++) {
        cp_wait2(); __syncthreads();
        loadst(it + 3);
        const uint4* SA = sm + (it & 3) * 1024;
        const uint2* SB = (const uint2*)(SA + 512);
#pragma unroll
        for (int kcl = 0; kcl < 4; kcl++) {
            uint4 a = SA[(kcl * 4 + mt) * 32 + lane];
#pragma unroll
            for (int jn = 0; jn < 4; jn++) {
                uint2 b = SB[(kcl * 8 + s * 4 + jn) * 32 + lane];
                mmabf(acc[jn], a, b);
            }
        }
    }
#pragma unroll
    for (int jn = 0; jn < 4; jn++) {
        int c8  = s * 4 + jn;
        int col = nb * 64 + c8 * 8 + cc * 2;
        float b0 = bp1[col], b1 = bp1[col + 1];
        int kcH = nb * 4 + (c8 >> 1);
        int regH_base = 2 * (c8 & 1);
#pragma unroll
        for (int hh = 0; hh < 2; hh++) {
            float v0 = fmaxf(acc[jn][hh * 2 + 0] + b0, 0.f);
            float v1 = fmaxf(acc[jn][hh * 2 + 1] + b1, 0.f);
            g_HIDp[((((size_t)mb * 16 + kcH) * 4 + mt) * 32 + (rr * 4 + cc)) * 4
                   + hh + regH_base] = pk(v0, v1);
        }
    }
}

// =================== head GEMM 2: logits = hid @ Wp2 + bp2 ===================
__global__ __launch_bounds__(256) void k_logitsb(const float* __restrict__ bp2,
                                                 float* __restrict__ out)
{
    extern __shared__ uint4 sm[];
    const int tid = threadIdx.x, wid = tid >> 5, lane = tid & 31;
    const int mt = wid & 3, s = wid >> 2;
    const int rr = lane >> 2, cc = lane & 3;
    const int nb = blockIdx.x, mb = blockIdx.y;
    float acc[4][4] = {};
    const uint4* A4 = (const uint4*)g_HIDp + (size_t)mb * 16 * 128;
    const uint4* B4 = (const uint4*)g_Wp2p + (size_t)nb * 16 * 128;

    auto loadst = [&](int it) {
        if (it < 4) {
            uint4* dst = sm + (it & 3) * 1024;
            const uint4* a = A4 + (size_t)it * 512;
            const uint4* b = B4 + (size_t)it * 512;
            cp16(&dst[tid],             &a[tid]);
            cp16(&dst[tid + 256],       &a[tid + 256]);
            cp16(&dst[512 + tid],       &b[tid]);
            cp16(&dst[512 + tid + 256], &b[tid + 256]);
        }
        cp_commit();
    };
    loadst(0); loadst(1); loadst(2);
    for (int it = 0; it < 4; it++) {
        cp_wait2(); __syncthreads();
        loadst(it + 3);
        const uint4* SA = sm + (it & 3) * 1024;
        const uint2* SB = (const uint2*)(SA + 512);
#pragma unroll
        for (int kcl = 0; kcl < 4; kcl++) {
            uint4 a = SA[(kcl * 4 + mt) * 32 + lane];
#pragma unroll
            for (int jn = 0; jn < 4; jn++) {
                uint2 b = SB[(kcl * 8 + s * 4 + jn) * 32 + lane];
                mmabf(acc[jn], a, b);
            }
        }
    }
#pragma unroll
    for (int jn = 0; jn < 4; jn++) {
        int n = nb * 64 + (s * 4 + jn) * 8 + cc * 2;
        if (n < NANS) {
            float b0 = bp2[n], b1 = bp2[n + 1];
#pragma unroll
            for (int hh = 0; hh < 2; hh++) {
                int m = mb * 64 + mt * 16 + rr + hh * 8;
                float* o = out + (size_t)m * NANS + n;
                o[0] = acc[jn][hh * 2 + 0] + b0;
                o[1] = acc[jn][hh * 2 + 1] + b1;
            }
        }
    }
}

// ---------------- softmax ------------------------------------------------------
__global__ __launch_bounds__(256) void k_softmax(float* __restrict__ out)
{
    __shared__ float red[256];
    const int tid = threadIdx.x;
    float* p = out + (size_t)blockIdx.x * NANS;
    float v[4];
    float mx = -1e30f;
#pragma unroll
    for (int i = 0; i < 4; i++) {
        int n = tid + i * 256;
        v[i] = (n < NANS) ? p[n] : -1e30f;
        mx = fmaxf(mx, v[i]);
    }
    red[tid] = mx; __syncthreads();
    for (int s = 128; s > 0; s >>= 1) {
        if (tid < s) red[tid] = fmaxf(red[tid], red[tid + s]);
        __syncthreads();
    }
    mx = red[0]; __syncthreads();
    float sum = 0.f;
#pragma unroll
    for (int i = 0; i < 4; i++) {
        int n = tid + i * 256;
        if (n < NANS) { v[i] = expf(v[i] - mx); sum += v[i]; }
    }
    red[tid] = sum; __syncthreads();
    for (int s = 128; s > 0; s >>= 1) {
        if (tid < s) red[tid] += red[tid + s];
        __syncthreads();
    }
    float inv = 1.f / red[0];
#pragma unroll
    for (int i = 0; i < 4; i++) {
        int n = tid + i * 256;
        if (n < NANS) p[n] = v[i] * inv;
    }
}

// ---------------- launch ------------------------------------------------------
extern "C" void kernel_launch(void* const* d_in, const int* in_sizes, int n_in,
                              void* d_out, int out_size)
{
    const float* data1 = (const float*)d_in[0];
    const float* data2 = (const float*)d_in[1];
    const float* W_ih1 = (const float*)d_in[2];
    const float* W_hh1 = (const float*)d_in[3];
    const float* b1    = (const float*)d_in[4];
    const float* W_ih2 = (const float*)d_in[5];
    const float* W_hh2 = (const float*)d_in[6];
    const float* b2    = (const float*)d_in[7];
    const float* Wp1   = (const float*)d_in[8];
    const float* bp1   = (const float*)d_in[9];
    const float* Wp2   = (const float*)d_in[10];
    const float* bp2   = (const float*)d_in[11];
    float* out = (float*)d_out;

    static bool attr_done = false;
    if (!attr_done) {
        cudaFuncSetAttribute(k_xprojb,  cudaFuncAttributeMaxDynamicSharedMemorySize, 196608);
        cudaFuncSetAttribute(k_mlp1b,   cudaFuncAttributeMaxDynamicSharedMemorySize, 65536);
        cudaFuncSetAttribute(k_logitsb, cudaFuncAttributeMaxDynamicSharedMemorySize, 65536);
        cudaFuncSetAttribute(k_recur,   cudaFuncAttributeMaxDynamicSharedMemorySize, 225280);
        attr_done = true;
    }

    k_init_state<<<128, 256>>>();
    k_pack_all<<<dim3(1024, 6), 256>>>(W_hh1, W_ih2, W_hh2, data1, data2,
                                       W_ih1, Wp1, Wp2);
    k_xprojb<<<dim3(16, 64), 256, 196608>>>(b1);
    k_recur<<<128, 256, 225280>>>(b2);
    k_mlp1b<<<dim3(4, 128), 256, 65536>>>(bp1);
    k_logitsb<<<dim3(16, 128), 256, 65536>>>(bp2, out);
    k_softmax<<<BT, 256>>>(out);
}